// round 3
// baseline (speedup 1.0000x reference)
#include <cuda_runtime.h>

// Langevin_2439541424651 — per-element independent 200-step recurrence.
// HBM-bound: 100MB noise read + 301MB output write. float4-vectorized,
// unroll-8 for ~28KB/SM bytes-in-flight, steps tensor folded in.

#define N_PART 1024
#define DX     128
#define STEPS  200
#define ND4    (N_PART * DX / 4)                  // 32768 float4 work items
#define TOT_XT ((long)N_PART * STEPS * DX)        // elems per [N,S,D] tensor

__global__ void __launch_bounds__(128) langevin_kernel(
    const float4* __restrict__ x0,      // [N*DX/4]
    const float4* __restrict__ y0,      // [N*DX/4]
    const float4* __restrict__ mean4,   // [DX/4]
    const float4* __restrict__ var4,    // [DX/4]
    const float*  __restrict__ gammas,  // [STEPS]
    const float4* __restrict__ noise,   // [STEPS * N * DX/4]
    float4* __restrict__ x_tot,         // [N, STEPS, DX/4]
    float4* __restrict__ y_tot,
    float4* __restrict__ out,
    float*  __restrict__ steps_out)     // [N, STEPS]
{
    __shared__ float s_g[STEPS];
    __shared__ float s_s[STEPS];

    for (int k = threadIdx.x; k < STEPS; k += blockDim.x) {
        float g = gammas[k];
        s_g[k] = g;
        s_s[k] = sqrtf(2.0f * g);
    }
    __syncthreads();

    int tid = blockIdx.x * blockDim.x + threadIdx.x;   // 0 .. ND4-1
    int d4  = tid & 31;                                // 32 float4 per row
    int n   = tid >> 5;
    bool lane0 = (d4 == 0);

    float4 x  = x0[tid];
    float4 yv = y0[tid];
    float4 m  = mean4[d4];
    float4 vv = var4[d4];
    float4 iv = make_float4(1.0f / vv.x, 1.0f / vv.y, 1.0f / vv.z, 1.0f / vv.w);

    long base = (long)n * STEPS * 32 + d4;             // in float4 units
    const float4* __restrict__ zp = noise + tid;
    float* __restrict__ sp = steps_out + (long)n * STEPS;

    // t_old = x - c*(x-m);  x_new = t_old + s*z
    // t_old - t_new = (t_old - x_new) + c*(x_new - m),  c = gamma/var
#pragma unroll 8
    for (int k = 0; k < STEPS; ++k) {
        float g = s_g[k];
        float s = s_s[k];
        float4 z = __ldcs(zp + (long)k * ND4);

        float4 xn, df;
        {
            float c = g * iv.x;
            float t = fmaf(-c, x.x - m.x, x.x);
            xn.x = fmaf(s, z.x, t);
            df.x = fmaf(c, xn.x - m.x, t - xn.x);
        }
        {
            float c = g * iv.y;
            float t = fmaf(-c, x.y - m.y, x.y);
            xn.y = fmaf(s, z.y, t);
            df.y = fmaf(c, xn.y - m.y, t - xn.y);
        }
        {
            float c = g * iv.z;
            float t = fmaf(-c, x.z - m.z, x.z);
            xn.z = fmaf(s, z.z, t);
            df.z = fmaf(c, xn.z - m.z, t - xn.z);
        }
        {
            float c = g * iv.w;
            float t = fmaf(-c, x.w - m.w, x.w);
            xn.w = fmaf(s, z.w, t);
            df.w = fmaf(c, xn.w - m.w, t - xn.w);
        }
        x = xn;

        long o = base + (long)k * 32;
        __stcs(x_tot + o, xn);
        __stcs(y_tot + o, yv);
        __stcs(out + o, df);
        if (lane0) __stcs(sp + k, (float)k);
    }
}

extern "C" void kernel_launch(void* const* d_in, const int* in_sizes, int n_in,
                              void* d_out, int out_size)
{
    const float* x0     = (const float*)d_in[0];
    const float* y0     = (const float*)d_in[1];
    const float* mean   = (const float*)d_in[2];
    const float* var    = (const float*)d_in[3];
    const float* gammas = (const float*)d_in[4];
    const float* noise  = (const float*)d_in[5];

    float* base  = (float*)d_out;
    float* x_tot = base;                 // [N, S, D]
    float* y_tot = base + TOT_XT;
    float* outp  = base + 2 * TOT_XT;
    float* steps = base + 3 * TOT_XT;    // [N, S, 1]

    langevin_kernel<<<ND4 / 128, 128>>>(
        (const float4*)x0, (const float4*)y0,
        (const float4*)mean, (const float4*)var,
        gammas, (const float4*)noise,
        (float4*)x_tot, (float4*)y_tot, (float4*)outp, steps);
}

// round 4
// speedup vs baseline: 1.1114x; 1.1114x over previous
#include <cuda_runtime.h>

// Langevin_2439541424651 — 131072 independent 200-step scalar recurrences.
// HBM-bound: ~100MB read + ~301MB write. Scalar threads maximize occupancy
// (thread count is capped by problem parallelism); unroll-8 supplies MLP.

#define N_PART 1024
#define DX     128
#define STEPS  200
#define ND     (N_PART * DX)                      // 131072
#define TOT_XT ((long)N_PART * STEPS * DX)

__global__ void __launch_bounds__(128) langevin_kernel(
    const float* __restrict__ x0,      // [N, DX]
    const float* __restrict__ y0,      // [N, DX]
    const float* __restrict__ mean,    // [DX]
    const float* __restrict__ var,     // [DX]
    const float* __restrict__ gammas,  // [STEPS]
    const float* __restrict__ noise,   // [STEPS, N, DX]
    float* __restrict__ x_tot,         // [N, STEPS, DX]
    float* __restrict__ y_tot,
    float* __restrict__ out,
    float* __restrict__ steps_out)     // [N, STEPS]
{
    __shared__ float s_g[STEPS];
    __shared__ float s_s[STEPS];

    for (int k = threadIdx.x; k < STEPS; k += blockDim.x) {
        float g = gammas[k];
        s_g[k] = g;
        s_s[k] = sqrtf(2.0f * g);
    }
    __syncthreads();

    int tid = blockIdx.x * blockDim.x + threadIdx.x;   // 0 .. ND-1
    int d = tid & (DX - 1);
    int n = tid >> 7;

    float x  = x0[tid];
    float yv = y0[tid];
    float m  = mean[d];
    float iv = 1.0f / var[d];

    long base = (long)n * STEPS * DX + d;
    const float* __restrict__ zp = noise + tid;
    float* __restrict__ sp = steps_out + (long)n * STEPS;
    bool lane0 = (d == 0);

    // t_old = x - c*(x-m);  x_new = t_old + s*z
    // t_old - t_new = (t_old - x_new) + c*(x_new - m),  c = gamma/var
#pragma unroll 8
    for (int k = 0; k < STEPS; ++k) {
        float g = s_g[k];
        float s = s_s[k];
        float z = __ldcs(zp + (long)k * ND);

        float c     = g * iv;
        float t_old = fmaf(-c, x - m, x);
        float xn    = fmaf(s, z, t_old);
        float diff  = fmaf(c, xn - m, t_old - xn);
        x = xn;

        long o = base + (long)k * DX;
        __stcs(x_tot + o, xn);
        __stcs(y_tot + o, yv);
        __stcs(out + o, diff);
        if (lane0) __stcs(sp + k, (float)k);
    }
}

extern "C" void kernel_launch(void* const* d_in, const int* in_sizes, int n_in,
                              void* d_out, int out_size)
{
    const float* x0     = (const float*)d_in[0];
    const float* y0     = (const float*)d_in[1];
    const float* mean   = (const float*)d_in[2];
    const float* var    = (const float*)d_in[3];
    const float* gammas = (const float*)d_in[4];
    const float* noise  = (const float*)d_in[5];

    float* base  = (float*)d_out;
    float* x_tot = base;                 // [N, S, D]
    float* y_tot = base + TOT_XT;
    float* outp  = base + 2 * TOT_XT;
    float* steps = base + 3 * TOT_XT;    // [N, S, 1]

    langevin_kernel<<<ND / 128, 128>>>(x0, y0, mean, var, gammas, noise,
                                       x_tot, y_tot, outp, steps);
}

// round 5
// speedup vs baseline: 1.9822x; 1.7835x over previous
#include <cuda_runtime.h>

// Langevin_2439541424651 — 131072 independent 200-step scalar recurrences.
// HBM-bound: ~100MB read + ~301MB write. Plain cached loads/stores (streaming
// .cs hints measurably regress on GB300: R3/R4 evidence). Scalar threads for
// max occupancy; unroll-8 scalar loads supply MLP within register budget.

#define N_PART 1024
#define DX     128
#define STEPS  200
#define ND     (N_PART * DX)                      // 131072 threads
#define TOT_XT ((long)N_PART * STEPS * DX)

__global__ void __launch_bounds__(256) langevin_kernel(
    const float* __restrict__ x0,      // [N, DX]
    const float* __restrict__ y0,      // [N, DX]
    const float* __restrict__ mean,    // [DX]
    const float* __restrict__ var,     // [DX]
    const float* __restrict__ gammas,  // [STEPS]
    const float* __restrict__ noise,   // [STEPS, N, DX]
    float* __restrict__ x_tot,         // [N, STEPS, DX]
    float* __restrict__ y_tot,
    float* __restrict__ out,
    float* __restrict__ steps_out)     // [N, STEPS]
{
    __shared__ float s_g[STEPS];
    __shared__ float s_s[STEPS];

    for (int k = threadIdx.x; k < STEPS; k += blockDim.x) {
        float g = gammas[k];
        s_g[k] = g;
        s_s[k] = sqrtf(2.0f * g);
    }

    int tid = blockIdx.x * blockDim.x + threadIdx.x;   // 0 .. ND-1

    // Steps tensor [N, STEPS, 1]: uniform coalesced prologue, no tail kernel.
    for (int i = tid; i < N_PART * STEPS; i += ND)
        steps_out[i] = (float)(i % STEPS);

    __syncthreads();

    int d = tid & (DX - 1);
    int n = tid >> 7;

    float x  = x0[tid];
    float yv = y0[tid];
    float m  = mean[d];
    float iv = 1.0f / var[d];

    long base = (long)n * STEPS * DX + d;
    const float* __restrict__ zp = noise + tid;

    // t_old = x - c*(x-m);  x_new = t_old + s*z
    // t_old - t_new = (t_old - x_new) + c*(x_new - m),  c = gamma/var
#pragma unroll 8
    for (int k = 0; k < STEPS; ++k) {
        float g = s_g[k];
        float s = s_s[k];
        float z = zp[(long)k * ND];

        float c     = g * iv;
        float t_old = fmaf(-c, x - m, x);
        float xn    = fmaf(s, z, t_old);
        float diff  = fmaf(c, xn - m, t_old - xn);
        x = xn;

        long o = base + (long)k * DX;
        x_tot[o] = xn;
        y_tot[o] = yv;
        out[o]   = diff;
    }
}

extern "C" void kernel_launch(void* const* d_in, const int* in_sizes, int n_in,
                              void* d_out, int out_size)
{
    const float* x0     = (const float*)d_in[0];
    const float* y0     = (const float*)d_in[1];
    const float* mean   = (const float*)d_in[2];
    const float* var    = (const float*)d_in[3];
    const float* gammas = (const float*)d_in[4];
    const float* noise  = (const float*)d_in[5];

    float* base  = (float*)d_out;
    float* x_tot = base;                 // [N, S, D]
    float* y_tot = base + TOT_XT;
    float* outp  = base + 2 * TOT_XT;
    float* steps = base + 3 * TOT_XT;    // [N, S, 1]

    langevin_kernel<<<ND / 256, 256>>>(x0, y0, mean, var, gammas, noise,
                                       x_tot, y_tot, outp, steps);
}